// round 16
// baseline (speedup 1.0000x reference)
#include <cuda_runtime.h>
#include <math.h>

// Problem constants
#define BATCH 2
#define SEQ 2048
#define DMODEL 1024
#define NHEADS 16
#define HDIM 64
#define MTOT (BATCH * SEQ)                 // 4096
#define OUT_ELEMS ((size_t)MTOT * DMODEL)  // 4,194,304
#define APH ((size_t)SEQ * SEQ)            // per-head attn elems

// Scratch (allocation-free rule: __device__ globals)
__device__ float g_q[MTOT * DMODEL];
__device__ float g_k[MTOT * DMODEL];
__device__ float g_v[MTOT * DMODEL];
__device__ float g_ctx[MTOT * DMODEL];
// Row-sum partials: [z(32)][ntile(16)][row(2048)]
__device__ float g_rsum[32 * 16 * 2048];

// ---------- tf32 / cp.async helpers ----------
__device__ __forceinline__ unsigned f2t(float x) {
    unsigned u;
    asm("cvt.rna.tf32.f32 %0, %1;" : "=r"(u) : "f"(x));
    return u;
}

__device__ __forceinline__ void mma8(float* d, const unsigned* a, const unsigned* b) {
    asm volatile(
        "mma.sync.aligned.m16n8k8.row.col.f32.tf32.tf32.f32 "
        "{%0,%1,%2,%3}, {%4,%5,%6,%7}, {%8,%9}, {%0,%1,%2,%3};\n"
        : "+f"(d[0]), "+f"(d[1]), "+f"(d[2]), "+f"(d[3])
        : "r"(a[0]), "r"(a[1]), "r"(a[2]), "r"(a[3]), "r"(b[0]), "r"(b[1]));
}

__device__ __forceinline__ unsigned sptr(const void* p) {
    return (unsigned)__cvta_generic_to_shared(p);
}
#define CPA(dst, src) \
    asm volatile("cp.async.cg.shared.global [%0], [%1], 16;\n" :: "r"(dst), "l"(src))
#define CPC() asm volatile("cp.async.commit_group;\n")
#define CPW0() asm volatile("cp.async.wait_group 0;\n" ::: "memory")
#define CPW1() asm volatile("cp.async.wait_group 1;\n" ::: "memory")
#define CPW2() asm volatile("cp.async.wait_group 2;\n" ::: "memory")

#define PBK 16     // K-chunk per smem stage
#define LDM 20     // m-major A-tile row stride (16 + 4 pad), words
#define LDN 132    // k-major B-tile row stride (128 + 4 pad), words
#define LDV 68     // k-major V-tile row stride (64 + 4), words
#define LDS2 68    // scores single-shot tile row stride (64 + 4), words

struct GemmArgs {
    const float* A;
    const float* W[3];
    const float* bias[3];
    float* C[3];
};

// ======================================================================
// GEMM: C[z][M,N] = A[M,K] @ W[z][K,N] + bias[z][N]
// CTA 128x128x16, 4 warps (64x64 each), cp.async 3-stage  [R14 config]
// ======================================================================
#define G_SA 2560   // 128*20 words per stage
#define G_SB 2112   // 16*132 words per stage

__global__ __launch_bounds__(128) void gemm3_tc(GemmArgs ga, int M, int N, int K)
{
    extern __shared__ float smem[];
    float* sAb = smem;              // 3 * G_SA
    float* sBb = smem + 3 * G_SA;   // 3 * G_SB

    int tid = threadIdx.x, lane = tid & 31, wid = tid >> 5;
    int grp = lane >> 2, tig = lane & 3;
    int m0 = blockIdx.y * 128, n0 = blockIdx.x * 128;
    int z = blockIdx.z;
    const float* A = ga.A;
    const float* B = ga.W[z];
    const float* bias = ga.bias[z];
    float* C = ga.C[z];

    int wm = (wid >> 1) * 64, wn = (wid & 1) * 64;
    int ar = tid >> 2, ac = (tid & 3) * 4;
    int br = tid >> 5, bc = (tid & 31) * 4;

    float acc[4][8][4] = {};

    auto issue = [&](int s, int k0) {
        float* pa = sAb + s * G_SA;
        float* pb = sBb + s * G_SB;
#pragma unroll
        for (int p = 0; p < 4; p++) {
            CPA(sptr(pa + (ar + p * 32) * LDM + ac),
                &A[(size_t)(m0 + ar + p * 32) * K + k0 + ac]);
            CPA(sptr(pb + (br + p * 4) * LDN + bc),
                &B[(size_t)(k0 + br + p * 4) * N + n0 + bc]);
        }
    };

    int NIT = K / PBK;
    issue(0, 0); CPC();
    issue(1, PBK); CPC();

    for (int it = 0; it < NIT; ++it) {
        CPW1();
        __syncthreads();
        int nx = it + 2;
        if (nx < NIT) issue(nx % 3, nx * PBK);
        CPC();
        const float* sa = sAb + (it % 3) * G_SA;
        const float* sb = sBb + (it % 3) * G_SB;
#pragma unroll
        for (int ks = 0; ks < 2; ks++) {
            int kk = ks * 8 + tig;
            unsigned af[4][4], bf8[8][2];
#pragma unroll
            for (int mi = 0; mi < 4; mi++) {
                int mb = wm + mi * 16 + grp;
                af[mi][0] = f2t(sa[mb * LDM + kk]);
                af[mi][1] = f2t(sa[(mb + 8) * LDM + kk]);
                af[mi][2] = f2t(sa[mb * LDM + kk + 4]);
                af[mi][3] = f2t(sa[(mb + 8) * LDM + kk + 4]);
            }
#pragma unroll
            for (int ni = 0; ni < 8; ni++) {
                int nb = wn + ni * 8 + grp;
                bf8[ni][0] = f2t(sb[kk * LDN + nb]);
                bf8[ni][1] = f2t(sb[(kk + 4) * LDN + nb]);
            }
#pragma unroll
            for (int mi = 0; mi < 4; mi++)
#pragma unroll
                for (int ni = 0; ni < 8; ni++) mma8(acc[mi][ni], af[mi], bf8[ni]);
        }
    }

#pragma unroll
    for (int mi = 0; mi < 4; mi++) {
        int row = m0 + wm + mi * 16 + grp;
#pragma unroll
        for (int ni = 0; ni < 8; ni++) {
            int col = n0 + wn + ni * 8 + 2 * tig;
            float b0 = bias[col], b1 = bias[col + 1];
            C[(size_t)row * N + col]           = acc[mi][ni][0] + b0;
            C[(size_t)row * N + col + 1]       = acc[mi][ni][1] + b1;
            C[(size_t)(row + 8) * N + col]     = acc[mi][ni][2] + b0;
            C[(size_t)(row + 8) * N + col + 1] = acc[mi][ni][3] + b1;
        }
    }
}

// ======================================================================
// Scores+exp (single-shot smem): load full 128x64 Q and K tiles once,
// then 8 uninterrupted k8-steps. attn = exp(QK^T * 0.125) unnormalized;
// per-row partial sums into g_rsum[z][ntile][row].
// ======================================================================
#define S_TILE (128 * LDS2)   // 8704 words per tensor

__global__ __launch_bounds__(128) void scores_exp_tc(
    const float* __restrict__ Q, const float* __restrict__ Km,
    float* __restrict__ attn)
{
    extern __shared__ float smem[];
    float* sQ = smem;            // 128 x LDS2
    float* sK = smem + S_TILE;   // 128 x LDS2
    __shared__ float srs[128];

    int tid = threadIdx.x, lane = tid & 31, wid = tid >> 5;
    int grp = lane >> 2, tig = lane & 3;
    int q0 = blockIdx.y * 128, n0 = blockIdx.x * 128;
    int z = blockIdx.z, b = z / NHEADS, h = z % NHEADS;
    int wm = (wid >> 1) * 64, wn = (wid & 1) * 64;
    int ar = tid >> 2;              // 0..31
    int kc = (tid & 3) * 16;        // 0,16,32,48

    srs[tid] = 0.f;

    const float* Qb = Q + (size_t)b * SEQ * DMODEL + h * HDIM;
    const float* Kb = Km + (size_t)b * SEQ * DMODEL + h * HDIM;

    // One-shot tile load: each thread 4 rows x 4 col-chunks per tensor
#pragma unroll
    for (int p = 0; p < 4; p++) {
        int row = ar + p * 32;
#pragma unroll
        for (int c = 0; c < 4; c++) {
            int col = kc + c * 4;
            CPA(sptr(sQ + row * LDS2 + col),
                &Qb[(size_t)(q0 + row) * DMODEL + col]);
            CPA(sptr(sK + row * LDS2 + col),
                &Kb[(size_t)(n0 + row) * DMODEL + col]);
        }
    }
    CPC();
    CPW0();
    __syncthreads();

    float acc[4][8][4] = {};

#pragma unroll
    for (int ks = 0; ks < 8; ks++) {
        int kk = ks * 8 + tig;
        unsigned af[4][4], bf8[8][2];
#pragma unroll
        for (int mi = 0; mi < 4; mi++) {
            int mb = wm + mi * 16 + grp;
            af[mi][0] = f2t(sQ[mb * LDS2 + kk]);
            af[mi][1] = f2t(sQ[(mb + 8) * LDS2 + kk]);
            af[mi][2] = f2t(sQ[mb * LDS2 + kk + 4]);
            af[mi][3] = f2t(sQ[(mb + 8) * LDS2 + kk + 4]);
        }
#pragma unroll
        for (int ni = 0; ni < 8; ni++) {
            int nb = wn + ni * 8 + grp;
            bf8[ni][0] = f2t(sK[nb * LDS2 + kk]);
            bf8[ni][1] = f2t(sK[nb * LDS2 + kk + 4]);
        }
#pragma unroll
        for (int mi = 0; mi < 4; mi++)
#pragma unroll
            for (int ni = 0; ni < 8; ni++) mma8(acc[mi][ni], af[mi], bf8[ni]);
    }

    // Epilogue: e = exp(scale*s); store; reduce row partials
    float* S = attn + (size_t)z * APH;
    const float scale = 0.125f;  // 1/sqrt(64)
#pragma unroll
    for (int mi = 0; mi < 4; mi++) {
        int row = q0 + wm + mi * 16 + grp;
        float r0 = 0.f, r1 = 0.f;
#pragma unroll
        for (int ni = 0; ni < 8; ni++) {
            int col = n0 + wn + ni * 8 + 2 * tig;
            float e0 = __expf(acc[mi][ni][0] * scale);
            float e1 = __expf(acc[mi][ni][1] * scale);
            float e2 = __expf(acc[mi][ni][2] * scale);
            float e3 = __expf(acc[mi][ni][3] * scale);
            S[(size_t)row * SEQ + col]           = e0;
            S[(size_t)row * SEQ + col + 1]       = e1;
            S[(size_t)(row + 8) * SEQ + col]     = e2;
            S[(size_t)(row + 8) * SEQ + col + 1] = e3;
            r0 += e0 + e1;
            r1 += e2 + e3;
        }
        r0 += __shfl_xor_sync(~0u, r0, 1); r0 += __shfl_xor_sync(~0u, r0, 2);
        r1 += __shfl_xor_sync(~0u, r1, 1); r1 += __shfl_xor_sync(~0u, r1, 2);
        if (tig == 0) {
            atomicAdd(&srs[wm + mi * 16 + grp], r0);
            atomicAdd(&srs[wm + mi * 16 + grp + 8], r1);
        }
    }
    __syncthreads();
    g_rsum[((size_t)z * 16 + blockIdx.x) * 2048 + q0 + tid] = srs[tid];
}

// ======================================================================
// AV + normalize: reads exp-attn, writes normalized attn back (streamed),
// ctx = (exp-attn @ V) * inv_row   (normalization in epilogue).
// CTA 256x64 full-K; 8 warps (32x64 each, M-split); cp.async 4-stage.
// Single wave: grid 256 CTAs @ 2/SM. No atomics.
// ======================================================================
#define V_SA 5120   // 256*20 words per stage
#define V_SB 1088   // 16*68 words per stage

__global__ __launch_bounds__(256, 2) void av_tc(
    float* __restrict__ attn, const float* __restrict__ V,
    float* __restrict__ ctx)
{
    extern __shared__ float smem[];
    float* sAb = smem;                         // 4 * V_SA
    float* sBb = smem + 4 * V_SA;              // 4 * V_SB
    float* sinv = smem + 4 * V_SA + 4 * V_SB;  // 256 row inverses

    int tid = threadIdx.x, lane = tid & 31, wid = tid >> 5;
    int grp = lane >> 2, tig = lane & 3;
    int m0 = blockIdx.x * 256;
    int z = blockIdx.y, b = z / NHEADS, h = z % NHEADS;
    int wm = wid * 32;                       // 8 warps split M, all share N=64
    int ar = tid >> 2, ac = (tid & 3) * 4;   // A: rows ar+p*64 (p<4), k-cols ac
    int rv = tid >> 4, cv = (tid & 15) * 4;  // V: k-row rv, n-cols cv

    float* Ab = attn + (size_t)z * APH;
    const float* Vb = V + (size_t)b * SEQ * DMODEL + h * HDIM;

    // Row inverse sums from the 16 scores partials
    {
        float s0 = 0.f;
        const float* rp = &g_rsum[(size_t)z * 16 * 2048 + m0];
#pragma unroll
        for (int t = 0; t < 16; t++) s0 += rp[t * 2048 + tid];
        sinv[tid] = 1.f / s0;
    }

    float acc[2][8][4] = {};

    auto issue = [&](int s, int k0) {
        float* pa = sAb + s * V_SA;
        float* pb = sBb + s * V_SB;
#pragma unroll
        for (int p = 0; p < 4; p++)
            CPA(sptr(pa + (ar + p * 64) * LDM + ac),
                &Ab[(size_t)(m0 + ar + p * 64) * SEQ + k0 + ac]);
        CPA(sptr(pb + rv * LDV + cv),
            &Vb[(size_t)(k0 + rv) * DMODEL + cv]);
    };

    const int NIT = SEQ / PBK;  // 128
    issue(0, 0); CPC();
    issue(1, PBK); CPC();
    issue(2, 2 * PBK); CPC();
    __syncthreads();   // sinv visible to all threads

    // Per-thread row inverses for the write-back rows (loop-invariant)
    float winv[4];
#pragma unroll
    for (int p = 0; p < 4; p++) winv[p] = sinv[ar + p * 64];

    for (int it = 0; it < NIT; ++it) {
        CPW2();
        __syncthreads();
        int nx = it + 3;
        if (nx < NIT) issue(nx & 3, nx * PBK);
        CPC();
        const float* sa = sAb + (it & 3) * V_SA;
        const float* sb = sBb + (it & 3) * V_SB;
#pragma unroll
        for (int ks = 0; ks < 2; ks++) {
            int kk = ks * 8 + tig;
            unsigned af[2][4], bf8[8][2];
#pragma unroll
            for (int mi = 0; mi < 2; mi++) {
                int mb = wm + mi * 16 + grp;
                af[mi][0] = f2t(sa[mb * LDM + kk]);
                af[mi][1] = f2t(sa[(mb + 8) * LDM + kk]);
                af[mi][2] = f2t(sa[mb * LDM + kk + 4]);
                af[mi][3] = f2t(sa[(mb + 8) * LDM + kk + 4]);
            }
#pragma unroll
            for (int ni = 0; ni < 8; ni++) {
                int nb = ni * 8 + grp;
                bf8[ni][0] = f2t(sb[kk * LDV + nb]);
                bf8[ni][1] = f2t(sb[(kk + 4) * LDV + nb]);
            }
#pragma unroll
            for (int mi = 0; mi < 2; mi++)
#pragma unroll
                for (int ni = 0; ni < 8; ni++) mma8(acc[mi][ni], af[mi], bf8[ni]);
        }
        // Write back normalized attn for this tile
        {
            int kg = it * PBK + ac;
#pragma unroll
            for (int p = 0; p < 4; p++) {
                const float* src = sa + (ar + p * 64) * LDM + ac;
                float4 t;
                t.x = src[0] * winv[p];
                t.y = src[1] * winv[p];
                t.z = src[2] * winv[p];
                t.w = src[3] * winv[p];
                *(float4*)&Ab[(size_t)(m0 + ar + p * 64) * SEQ + kg] = t;
            }
        }
    }

    // Epilogue: normalized ctx (plain stores — full K in this CTA)
    float* Cb = ctx + (size_t)b * SEQ * DMODEL + h * HDIM;
#pragma unroll
    for (int mi = 0; mi < 2; mi++) {
        int mb = wm + mi * 16 + grp;
        int row = m0 + mb;
        float i0 = sinv[mb], i1 = sinv[mb + 8];
#pragma unroll
        for (int ni = 0; ni < 8; ni++) {
            int col = ni * 8 + 2 * tig;
            Cb[(size_t)row * DMODEL + col]           = acc[mi][ni][0] * i0;
            Cb[(size_t)row * DMODEL + col + 1]       = acc[mi][ni][1] * i0;
            Cb[(size_t)(row + 8) * DMODEL + col]     = acc[mi][ni][2] * i1;
            Cb[(size_t)(row + 8) * DMODEL + col + 1] = acc[mi][ni][3] * i1;
        }
    }
}

extern "C" void kernel_launch(void* const* d_in, const int* in_sizes, int n_in,
                              void* d_out, int out_size) {
    const float* x   = (const float*)d_in[0];
    const float* w_q = (const float*)d_in[1];
    const float* b_q = (const float*)d_in[2];
    const float* w_k = (const float*)d_in[3];
    const float* b_k = (const float*)d_in[4];
    const float* w_v = (const float*)d_in[5];
    const float* b_v = (const float*)d_in[6];
    const float* w_o = (const float*)d_in[7];
    const float* b_o = (const float*)d_in[8];

    float* out  = (float*)d_out;
    float* attn = out + OUT_ELEMS;

    float *q, *k, *v, *ctx;
    cudaGetSymbolAddress((void**)&q,   g_q);
    cudaGetSymbolAddress((void**)&k,   g_k);
    cudaGetSymbolAddress((void**)&v,   g_v);
    cudaGetSymbolAddress((void**)&ctx, g_ctx);

    const int gemmSmem   = (3 * G_SA + 3 * G_SB) * 4;          // 56064 B
    const int scoresSmem = (2 * S_TILE) * 4;                   // 69632 B
    const int avSmem     = (4 * V_SA + 4 * V_SB + 256) * 4;    // 100352 B
    cudaFuncSetAttribute(gemm3_tc,      cudaFuncAttributeMaxDynamicSharedMemorySize, gemmSmem);
    cudaFuncSetAttribute(scores_exp_tc, cudaFuncAttributeMaxDynamicSharedMemorySize, scoresSmem);
    cudaFuncSetAttribute(av_tc,         cudaFuncAttributeMaxDynamicSharedMemorySize, avSmem);

    // Fused QKV projections
    GemmArgs qkv;
    qkv.A = x;
    qkv.W[0] = w_q; qkv.W[1] = w_k; qkv.W[2] = w_v;
    qkv.bias[0] = b_q; qkv.bias[1] = b_k; qkv.bias[2] = b_v;
    qkv.C[0] = q; qkv.C[1] = k; qkv.C[2] = v;
    dim3 g1(DMODEL / 128, MTOT / 128, 3);
    gemm3_tc<<<g1, 128, gemmSmem>>>(qkv, MTOT, DMODEL, DMODEL);

    // Scores + exp + row-sum partials (single-shot smem)
    dim3 g2(SEQ / 128, SEQ / 128, BATCH * NHEADS);
    scores_exp_tc<<<g2, 128, scoresSmem>>>(q, k, attn);

    // ctx = softmax @ V (normalization fused); normalized attn written back
    dim3 g3(SEQ / 256, BATCH * NHEADS);
    av_tc<<<g3, 256, avSmem>>>(attn, v, ctx);

    // out = ctx @ w_o + b_o (single launch, bias epilogue)
    GemmArgs op;
    op.A = ctx;
    op.W[0] = w_o; op.W[1] = w_o; op.W[2] = w_o;
    op.bias[0] = b_o; op.bias[1] = b_o; op.bias[2] = b_o;
    op.C[0] = out; op.C[1] = out; op.C[2] = out;
    dim3 g4(DMODEL / 128, MTOT / 128, 1);
    gemm3_tc<<<g4, 128, gemmSmem>>>(op, MTOT, DMODEL, DMODEL);
}

// round 17
// speedup vs baseline: 1.6024x; 1.6024x over previous
#include <cuda_runtime.h>
#include <math.h>

// Problem constants
#define BATCH 2
#define SEQ 2048
#define DMODEL 1024
#define NHEADS 16
#define HDIM 64
#define MTOT (BATCH * SEQ)                 // 4096
#define OUT_ELEMS ((size_t)MTOT * DMODEL)  // 4,194,304
#define APH ((size_t)SEQ * SEQ)            // per-head attn elems

// Scratch (allocation-free rule: __device__ globals)
__device__ float g_q[MTOT * DMODEL];
__device__ float g_k[MTOT * DMODEL];
__device__ float g_v[MTOT * DMODEL];
__device__ float g_ctx[MTOT * DMODEL];
// Row-sum partials: [z(32)][ntile(16)][row(2048)]
__device__ float g_rsum[32 * 16 * 2048];

// ---------- tf32 / cp.async helpers ----------
__device__ __forceinline__ unsigned f2t(float x) {
    unsigned u;
    asm("cvt.rna.tf32.f32 %0, %1;" : "=r"(u) : "f"(x));
    return u;
}

__device__ __forceinline__ void mma8(float* d, const unsigned* a, const unsigned* b) {
    asm volatile(
        "mma.sync.aligned.m16n8k8.row.col.f32.tf32.tf32.f32 "
        "{%0,%1,%2,%3}, {%4,%5,%6,%7}, {%8,%9}, {%0,%1,%2,%3};\n"
        : "+f"(d[0]), "+f"(d[1]), "+f"(d[2]), "+f"(d[3])
        : "r"(a[0]), "r"(a[1]), "r"(a[2]), "r"(a[3]), "r"(b[0]), "r"(b[1]));
}

__device__ __forceinline__ unsigned sptr(const void* p) {
    return (unsigned)__cvta_generic_to_shared(p);
}
#define CPA(dst, src) \
    asm volatile("cp.async.cg.shared.global [%0], [%1], 16;\n" :: "r"(dst), "l"(src))
#define CPC() asm volatile("cp.async.commit_group;\n")
#define CPW1() asm volatile("cp.async.wait_group 1;\n" ::: "memory")
#define CPW2() asm volatile("cp.async.wait_group 2;\n" ::: "memory")

#define PBK 16     // K-chunk per smem stage
#define LDM 20     // m-major A-tile row stride (16 + 4 pad), words
#define LDN 132    // k-major B-tile row stride (128 + 4 pad), words
#define LDV 68     // k-major V-tile row stride (64 + 4), words

struct GemmArgs {
    const float* A;
    const float* W[3];
    const float* bias[3];
    float* C[3];
};

// ======================================================================
// GEMM: C[z][M,N] = A[M,K] @ W[z][K,N] + bias[z][N]
// CTA 128x128x16, 4 warps (64x64 each), cp.async 4-stage
// ======================================================================
#define G_SA 2560   // 128*20 words per stage
#define G_SB 2112   // 16*132 words per stage

__global__ __launch_bounds__(128) void gemm3_tc(GemmArgs ga, int M, int N, int K)
{
    extern __shared__ float smem[];
    float* sAb = smem;              // 4 * G_SA
    float* sBb = smem + 4 * G_SA;   // 4 * G_SB

    int tid = threadIdx.x, lane = tid & 31, wid = tid >> 5;
    int grp = lane >> 2, tig = lane & 3;
    int m0 = blockIdx.y * 128, n0 = blockIdx.x * 128;
    int z = blockIdx.z;
    const float* A = ga.A;
    const float* B = ga.W[z];
    const float* bias = ga.bias[z];
    float* C = ga.C[z];

    int wm = (wid >> 1) * 64, wn = (wid & 1) * 64;
    int ar = tid >> 2, ac = (tid & 3) * 4;
    int br = tid >> 5, bc = (tid & 31) * 4;

    float acc[4][8][4] = {};

    auto issue = [&](int s, int k0) {
        float* pa = sAb + s * G_SA;
        float* pb = sBb + s * G_SB;
#pragma unroll
        for (int p = 0; p < 4; p++) {
            CPA(sptr(pa + (ar + p * 32) * LDM + ac),
                &A[(size_t)(m0 + ar + p * 32) * K + k0 + ac]);
            CPA(sptr(pb + (br + p * 4) * LDN + bc),
                &B[(size_t)(k0 + br + p * 4) * N + n0 + bc]);
        }
    };

    int NIT = K / PBK;
    issue(0, 0); CPC();
    issue(1, PBK); CPC();
    issue(2, 2 * PBK); CPC();

    for (int it = 0; it < NIT; ++it) {
        CPW2();
        __syncthreads();
        int nx = it + 3;
        if (nx < NIT) issue(nx & 3, nx * PBK);
        CPC();
        const float* sa = sAb + (it & 3) * G_SA;
        const float* sb = sBb + (it & 3) * G_SB;
#pragma unroll
        for (int ks = 0; ks < 2; ks++) {
            int kk = ks * 8 + tig;
            unsigned af[4][4], bf8[8][2];
#pragma unroll
            for (int mi = 0; mi < 4; mi++) {
                int mb = wm + mi * 16 + grp;
                af[mi][0] = f2t(sa[mb * LDM + kk]);
                af[mi][1] = f2t(sa[(mb + 8) * LDM + kk]);
                af[mi][2] = f2t(sa[mb * LDM + kk + 4]);
                af[mi][3] = f2t(sa[(mb + 8) * LDM + kk + 4]);
            }
#pragma unroll
            for (int ni = 0; ni < 8; ni++) {
                int nb = wn + ni * 8 + grp;
                bf8[ni][0] = f2t(sb[kk * LDN + nb]);
                bf8[ni][1] = f2t(sb[(kk + 4) * LDN + nb]);
            }
#pragma unroll
            for (int mi = 0; mi < 4; mi++)
#pragma unroll
                for (int ni = 0; ni < 8; ni++) mma8(acc[mi][ni], af[mi], bf8[ni]);
        }
    }

#pragma unroll
    for (int mi = 0; mi < 4; mi++) {
        int row = m0 + wm + mi * 16 + grp;
#pragma unroll
        for (int ni = 0; ni < 8; ni++) {
            int col = n0 + wn + ni * 8 + 2 * tig;
            float b0 = bias[col], b1 = bias[col + 1];
            C[(size_t)row * N + col]           = acc[mi][ni][0] + b0;
            C[(size_t)row * N + col + 1]       = acc[mi][ni][1] + b1;
            C[(size_t)(row + 8) * N + col]     = acc[mi][ni][2] + b0;
            C[(size_t)(row + 8) * N + col + 1] = acc[mi][ni][3] + b1;
        }
    }
}

// ======================================================================
// Scores+exp: attn[z,q,k] = exp((Q_z@K_z^T)*0.125) (UNNORMALIZED) +
// per-row partial sums into g_rsum[z][ntile][row].  [R14 pipelined]
// ======================================================================
#define S_ST 2560   // 128*20 words per stage

__global__ __launch_bounds__(128) void scores_exp_tc(
    const float* __restrict__ Q, const float* __restrict__ Km,
    float* __restrict__ attn)
{
    extern __shared__ float smem[];
    float* sAb = smem;
    float* sBb = smem + 3 * S_ST;
    __shared__ float srs[128];

    int tid = threadIdx.x, lane = tid & 31, wid = tid >> 5;
    int grp = lane >> 2, tig = lane & 3;
    int q0 = blockIdx.y * 128, n0 = blockIdx.x * 128;
    int z = blockIdx.z, b = z / NHEADS, h = z % NHEADS;
    int wm = (wid >> 1) * 64, wn = (wid & 1) * 64;
    int ar = tid >> 2, ac = (tid & 3) * 4;

    srs[tid] = 0.f;

    const float* Qb = Q + (size_t)b * SEQ * DMODEL + h * HDIM;
    const float* Kb = Km + (size_t)b * SEQ * DMODEL + h * HDIM;

    float acc[4][8][4] = {};

    auto issue = [&](int s, int k0) {
        float* pa = sAb + s * S_ST;
        float* pb = sBb + s * S_ST;
#pragma unroll
        for (int p = 0; p < 4; p++) {
            CPA(sptr(pa + (ar + p * 32) * LDM + ac),
                &Qb[(size_t)(q0 + ar + p * 32) * DMODEL + k0 + ac]);
            CPA(sptr(pb + (ar + p * 32) * LDM + ac),
                &Kb[(size_t)(n0 + ar + p * 32) * DMODEL + k0 + ac]);
        }
    };

    const int NIT = HDIM / PBK;  // 4
    issue(0, 0); CPC();
    issue(1, PBK); CPC();

    for (int it = 0; it < NIT; ++it) {
        CPW1();
        __syncthreads();
        int nx = it + 2;
        if (nx < NIT) issue(nx % 3, nx * PBK);
        CPC();
        const float* sa = sAb + (it % 3) * S_ST;
        const float* sb = sBb + (it % 3) * S_ST;
#pragma unroll
        for (int ks = 0; ks < 2; ks++) {
            int kk = ks * 8 + tig;
            unsigned af[4][4], bf8[8][2];
#pragma unroll
            for (int mi = 0; mi < 4; mi++) {
                int mb = wm + mi * 16 + grp;
                af[mi][0] = f2t(sa[mb * LDM + kk]);
                af[mi][1] = f2t(sa[(mb + 8) * LDM + kk]);
                af[mi][2] = f2t(sa[mb * LDM + kk + 4]);
                af[mi][3] = f2t(sa[(mb + 8) * LDM + kk + 4]);
            }
#pragma unroll
            for (int ni = 0; ni < 8; ni++) {
                int nb = wn + ni * 8 + grp;
                bf8[ni][0] = f2t(sb[nb * LDM + kk]);
                bf8[ni][1] = f2t(sb[nb * LDM + kk + 4]);
            }
#pragma unroll
            for (int mi = 0; mi < 4; mi++)
#pragma unroll
                for (int ni = 0; ni < 8; ni++) mma8(acc[mi][ni], af[mi], bf8[ni]);
        }
    }

    // Epilogue: e = exp(scale*s); store; reduce row partials
    float* S = attn + (size_t)z * APH;
    const float scale = 0.125f;  // 1/sqrt(64)
#pragma unroll
    for (int mi = 0; mi < 4; mi++) {
        int row = q0 + wm + mi * 16 + grp;
        float r0 = 0.f, r1 = 0.f;
#pragma unroll
        for (int ni = 0; ni < 8; ni++) {
            int col = n0 + wn + ni * 8 + 2 * tig;
            float e0 = __expf(acc[mi][ni][0] * scale);
            float e1 = __expf(acc[mi][ni][1] * scale);
            float e2 = __expf(acc[mi][ni][2] * scale);
            float e3 = __expf(acc[mi][ni][3] * scale);
            S[(size_t)row * SEQ + col]           = e0;
            S[(size_t)row * SEQ + col + 1]       = e1;
            S[(size_t)(row + 8) * SEQ + col]     = e2;
            S[(size_t)(row + 8) * SEQ + col + 1] = e3;
            r0 += e0 + e1;
            r1 += e2 + e3;
        }
        r0 += __shfl_xor_sync(~0u, r0, 1); r0 += __shfl_xor_sync(~0u, r0, 2);
        r1 += __shfl_xor_sync(~0u, r1, 1); r1 += __shfl_xor_sync(~0u, r1, 2);
        if (tig == 0) {
            atomicAdd(&srs[wm + mi * 16 + grp], r0);
            atomicAdd(&srs[wm + mi * 16 + grp + 8], r1);
        }
    }
    __syncthreads();
    g_rsum[((size_t)z * 16 + blockIdx.x) * 2048 + q0 + tid] = srs[tid];
}

// ======================================================================
// AV + normalize: reads exp-attn, writes normalized attn back (streamed),
// ctx = (exp-attn @ V) * inv_row   (normalization in epilogue).
// CTA 256x64 full-K; 8 warps (32x64 each, M-split); cp.async 4-stage.
// Single wave: grid 256 CTAs @ 2/SM. No atomics.  [R14 config]
// ======================================================================
#define V_SA 5120   // 256*20 words per stage
#define V_SB 1088   // 16*68 words per stage

__global__ __launch_bounds__(256, 2) void av_tc(
    float* __restrict__ attn, const float* __restrict__ V,
    float* __restrict__ ctx)
{
    extern __shared__ float smem[];
    float* sAb = smem;                         // 4 * V_SA
    float* sBb = smem + 4 * V_SA;              // 4 * V_SB
    float* sinv = smem + 4 * V_SA + 4 * V_SB;  // 256 row inverses

    int tid = threadIdx.x, lane = tid & 31, wid = tid >> 5;
    int grp = lane >> 2, tig = lane & 3;
    int m0 = blockIdx.x * 256;
    int z = blockIdx.y, b = z / NHEADS, h = z % NHEADS;
    int wm = wid * 32;                       // 8 warps split M, all share N=64
    int ar = tid >> 2, ac = (tid & 3) * 4;   // A: rows ar+p*64 (p<4), k-cols ac
    int rv = tid >> 4, cv = (tid & 15) * 4;  // V: k-row rv, n-cols cv

    float* Ab = attn + (size_t)z * APH;
    const float* Vb = V + (size_t)b * SEQ * DMODEL + h * HDIM;

    // Row inverse sums from the 16 scores partials
    {
        float s0 = 0.f;
        const float* rp = &g_rsum[(size_t)z * 16 * 2048 + m0];
#pragma unroll
        for (int t = 0; t < 16; t++) s0 += rp[t * 2048 + tid];
        sinv[tid] = 1.f / s0;
    }

    float acc[2][8][4] = {};

    auto issue = [&](int s, int k0) {
        float* pa = sAb + s * V_SA;
        float* pb = sBb + s * V_SB;
#pragma unroll
        for (int p = 0; p < 4; p++)
            CPA(sptr(pa + (ar + p * 64) * LDM + ac),
                &Ab[(size_t)(m0 + ar + p * 64) * SEQ + k0 + ac]);
        CPA(sptr(pb + rv * LDV + cv),
            &Vb[(size_t)(k0 + rv) * DMODEL + cv]);
    };

    const int NIT = SEQ / PBK;  // 128
    issue(0, 0); CPC();
    issue(1, PBK); CPC();
    issue(2, 2 * PBK); CPC();
    __syncthreads();   // sinv visible to all threads

    // Per-thread row inverses for the write-back rows (loop-invariant)
    float winv[4];
#pragma unroll
    for (int p = 0; p < 4; p++) winv[p] = sinv[ar + p * 64];

    for (int it = 0; it < NIT; ++it) {
        CPW2();
        __syncthreads();
        int nx = it + 3;
        if (nx < NIT) issue(nx & 3, nx * PBK);
        CPC();
        const float* sa = sAb + (it & 3) * V_SA;
        const float* sb = sBb + (it & 3) * V_SB;
#pragma unroll
        for (int ks = 0; ks < 2; ks++) {
            int kk = ks * 8 + tig;
            unsigned af[2][4], bf8[8][2];
#pragma unroll
            for (int mi = 0; mi < 2; mi++) {
                int mb = wm + mi * 16 + grp;
                af[mi][0] = f2t(sa[mb * LDM + kk]);
                af[mi][1] = f2t(sa[(mb + 8) * LDM + kk]);
                af[mi][2] = f2t(sa[mb * LDM + kk + 4]);
                af[mi][3] = f2t(sa[(mb + 8) * LDM + kk + 4]);
            }
#pragma unroll
            for (int ni = 0; ni < 8; ni++) {
                int nb = ni * 8 + grp;
                bf8[ni][0] = f2t(sb[kk * LDV + nb]);
                bf8[ni][1] = f2t(sb[(kk + 4) * LDV + nb]);
            }
#pragma unroll
            for (int mi = 0; mi < 2; mi++)
#pragma unroll
                for (int ni = 0; ni < 8; ni++) mma8(acc[mi][ni], af[mi], bf8[ni]);
        }
        // Write back normalized attn for this tile
        {
            int kg = it * PBK + ac;
#pragma unroll
            for (int p = 0; p < 4; p++) {
                const float* src = sa + (ar + p * 64) * LDM + ac;
                float4 t;
                t.x = src[0] * winv[p];
                t.y = src[1] * winv[p];
                t.z = src[2] * winv[p];
                t.w = src[3] * winv[p];
                *(float4*)&Ab[(size_t)(m0 + ar + p * 64) * SEQ + kg] = t;
            }
        }
    }

    // Epilogue: normalized ctx (plain stores — full K in this CTA)
    float* Cb = ctx + (size_t)b * SEQ * DMODEL + h * HDIM;
#pragma unroll
    for (int mi = 0; mi < 2; mi++) {
        int mb = wm + mi * 16 + grp;
        int row = m0 + mb;
        float i0 = sinv[mb], i1 = sinv[mb + 8];
#pragma unroll
        for (int ni = 0; ni < 8; ni++) {
            int col = ni * 8 + 2 * tig;
            Cb[(size_t)row * DMODEL + col]           = acc[mi][ni][0] * i0;
            Cb[(size_t)row * DMODEL + col + 1]       = acc[mi][ni][1] * i0;
            Cb[(size_t)(row + 8) * DMODEL + col]     = acc[mi][ni][2] * i1;
            Cb[(size_t)(row + 8) * DMODEL + col + 1] = acc[mi][ni][3] * i1;
        }
    }
}

extern "C" void kernel_launch(void* const* d_in, const int* in_sizes, int n_in,
                              void* d_out, int out_size) {
    const float* x   = (const float*)d_in[0];
    const float* w_q = (const float*)d_in[1];
    const float* b_q = (const float*)d_in[2];
    const float* w_k = (const float*)d_in[3];
    const float* b_k = (const float*)d_in[4];
    const float* w_v = (const float*)d_in[5];
    const float* b_v = (const float*)d_in[6];
    const float* w_o = (const float*)d_in[7];
    const float* b_o = (const float*)d_in[8];

    float* out  = (float*)d_out;
    float* attn = out + OUT_ELEMS;

    float *q, *k, *v, *ctx;
    cudaGetSymbolAddress((void**)&q,   g_q);
    cudaGetSymbolAddress((void**)&k,   g_k);
    cudaGetSymbolAddress((void**)&v,   g_v);
    cudaGetSymbolAddress((void**)&ctx, g_ctx);

    const int gemmSmem   = (4 * G_SA + 4 * G_SB) * 4;          // 74752 B
    const int scoresSmem = (6 * S_ST) * 4;                     // 61440 B
    const int avSmem     = (4 * V_SA + 4 * V_SB + 256) * 4;    // 100352 B
    cudaFuncSetAttribute(gemm3_tc,      cudaFuncAttributeMaxDynamicSharedMemorySize, gemmSmem);
    cudaFuncSetAttribute(scores_exp_tc, cudaFuncAttributeMaxDynamicSharedMemorySize, scoresSmem);
    cudaFuncSetAttribute(av_tc,         cudaFuncAttributeMaxDynamicSharedMemorySize, avSmem);

    // Fused QKV projections
    GemmArgs qkv;
    qkv.A = x;
    qkv.W[0] = w_q; qkv.W[1] = w_k; qkv.W[2] = w_v;
    qkv.bias[0] = b_q; qkv.bias[1] = b_k; qkv.bias[2] = b_v;
    qkv.C[0] = q; qkv.C[1] = k; qkv.C[2] = v;
    dim3 g1(DMODEL / 128, MTOT / 128, 3);
    gemm3_tc<<<g1, 128, gemmSmem>>>(qkv, MTOT, DMODEL, DMODEL);

    // Scores + exp + row-sum partials
    dim3 g2(SEQ / 128, SEQ / 128, BATCH * NHEADS);
    scores_exp_tc<<<g2, 128, scoresSmem>>>(q, k, attn);

    // ctx = softmax @ V (normalization fused); normalized attn written back
    dim3 g3(SEQ / 256, BATCH * NHEADS);
    av_tc<<<g3, 256, avSmem>>>(attn, v, ctx);

    // out = ctx @ w_o + b_o (single launch, bias epilogue)
    GemmArgs op;
    op.A = ctx;
    op.W[0] = w_o; op.W[1] = w_o; op.W[2] = w_o;
    op.bias[0] = b_o; op.bias[1] = b_o; op.bias[2] = b_o;
    op.C[0] = out; op.C[1] = out; op.C[2] = out;
    dim3 g4(DMODEL / 128, MTOT / 128, 1);
    gemm3_tc<<<g4, 128, gemmSmem>>>(op, MTOT, DMODEL, DMODEL);
}